// round 3
// baseline (speedup 1.0000x reference)
#include <cuda_runtime.h>
#include <cstdint>
#include <math.h>

#define E_ 8
#define D_ 2048
#define H_ 8192
#define R_ 64
#define N_ 4096
#define MAX_TILES 136
#define P_PAD (MAX_TILES*64)

__device__ __align__(16) float g_xh [(size_t)N_*D_];
__device__ __align__(16) float g_xl [(size_t)N_*D_];
__device__ __align__(16) float g_u1t[(size_t)E_*D_*R_];
__device__ __align__(16) float g_v1t[(size_t)E_*R_*H_];
__device__ __align__(16) float g_u2t[(size_t)E_*H_*R_];
__device__ __align__(16) float g_v2t[(size_t)E_*R_*D_];
__device__ __align__(16) float g_t1h[(size_t)P_PAD*R_];
__device__ __align__(16) float g_t1l[(size_t)P_PAD*R_];
__device__ __align__(16) float g_t2h[(size_t)P_PAD*R_];
__device__ __align__(16) float g_t2l[(size_t)P_PAD*R_];
__device__ __align__(16) float g_py [(size_t)P_PAD*D_];
__device__ int   g_ptok[P_PAD];
__device__ float g_pw  [P_PAD];
__device__ int   g_entry[2*N_];
__device__ int   g_re[2*N_];
__device__ float g_rw[2*N_];
__device__ int   g_cnt[E_];
__device__ int   g_cur[E_];
__device__ int   g_texp[MAX_TILES];

__device__ __forceinline__ float rna_tf32(float f) {
    uint32_t u; asm("cvt.rna.tf32.f32 %0, %1;" : "=r"(u) : "f"(f));
    return __uint_as_float(u);
}
__device__ __forceinline__ void mma8(float c[4], const float a[4], uint32_t b0, uint32_t b1) {
    asm volatile("mma.sync.aligned.m16n8k8.row.col.f32.tf32.tf32.f32 "
        "{%0,%1,%2,%3}, {%4,%5,%6,%7}, {%8,%9}, {%0,%1,%2,%3};"
        : "+f"(c[0]), "+f"(c[1]), "+f"(c[2]), "+f"(c[3])
        : "r"(__float_as_uint(a[0])), "r"(__float_as_uint(a[1])),
          "r"(__float_as_uint(a[2])), "r"(__float_as_uint(a[3])), "r"(b0), "r"(b1));
}
__device__ __forceinline__ void ldA(float a[4], const float* s, int st, int r, int k) {
    a[0]=s[r*st+k]; a[1]=s[(r+8)*st+k]; a[2]=s[r*st+k+4]; a[3]=s[(r+8)*st+k+4];
}
__device__ __forceinline__ void ldB(uint32_t& b0, uint32_t& b1, const float* s, int st, int k, int n) {
    b0=__float_as_uint(s[k*st+n]); b1=__float_as_uint(s[(k+4)*st+n]);
}
__device__ __forceinline__ void cpa(void* s, const void* g) {
    uint32_t sa=(uint32_t)__cvta_generic_to_shared(s);
    asm volatile("cp.async.cg.shared.global [%0], [%1], 16;" :: "r"(sa), "l"(g));
}
#define CPC  asm volatile("cp.async.commit_group;" ::: "memory")
#define CPW1 asm volatile("cp.async.wait_group 1;" ::: "memory")
#define CPW0 asm volatile("cp.async.wait_group 0;" ::: "memory")

__global__ void k_init() { if (threadIdx.x < E_) g_cnt[threadIdx.x] = 0; }

__global__ void k_pre(const float* __restrict__ u1, const float* __restrict__ v1,
                      const float* __restrict__ u2, const float* __restrict__ v2,
                      const float* __restrict__ x) {
    const int S1=E_*D_*R_/4, S2=E_*R_*H_/4, S3=E_*H_*R_/4, S4=E_*R_*D_/4, SX=N_*D_/4;
    int tid = blockIdx.x*blockDim.x + threadIdx.x, st = gridDim.x*blockDim.x;
    for (int i=tid;i<S1;i+=st){float4 v=((const float4*)u1)[i];
        v.x=rna_tf32(v.x);v.y=rna_tf32(v.y);v.z=rna_tf32(v.z);v.w=rna_tf32(v.w);((float4*)g_u1t)[i]=v;}
    for (int i=tid;i<S2;i+=st){float4 v=((const float4*)v1)[i];
        v.x=rna_tf32(v.x);v.y=rna_tf32(v.y);v.z=rna_tf32(v.z);v.w=rna_tf32(v.w);((float4*)g_v1t)[i]=v;}
    for (int i=tid;i<S3;i+=st){float4 v=((const float4*)u2)[i];
        v.x=rna_tf32(v.x);v.y=rna_tf32(v.y);v.z=rna_tf32(v.z);v.w=rna_tf32(v.w);((float4*)g_u2t)[i]=v;}
    for (int i=tid;i<S4;i+=st){float4 v=((const float4*)v2)[i];
        v.x=rna_tf32(v.x);v.y=rna_tf32(v.y);v.z=rna_tf32(v.z);v.w=rna_tf32(v.w);((float4*)g_v2t)[i]=v;}
    for (int i=tid;i<SX;i+=st){float4 v=((const float4*)x)[i]; float4 h,l;
        h.x=rna_tf32(v.x);l.x=rna_tf32(v.x-h.x); h.y=rna_tf32(v.y);l.y=rna_tf32(v.y-h.y);
        h.z=rna_tf32(v.z);l.z=rna_tf32(v.z-h.z); h.w=rna_tf32(v.w);l.w=rna_tf32(v.w-h.w);
        ((float4*)g_xh)[i]=h; ((float4*)g_xl)[i]=l;}
}

__global__ __launch_bounds__(256) void k_route(const float* __restrict__ x,
        const float* __restrict__ gw, const float* __restrict__ gb) {
    int warp=threadIdx.x>>5, lane=threadIdx.x&31;
    int n = blockIdx.x*8 + warp;
    const float4* xr = (const float4*)(x + (size_t)n*D_);
    float4 xv[16];
#pragma unroll
    for (int i=0;i<16;i++) xv[i]=xr[lane+i*32];
    float lg[8];
#pragma unroll
    for (int e=0;e<8;e++){
        const float4* gr=(const float4*)(gw+(size_t)e*D_);
        float s=0.f;
#pragma unroll
        for (int i=0;i<16;i++){float4 g=gr[lane+i*32];
            s+=xv[i].x*g.x+xv[i].y*g.y+xv[i].z*g.z+xv[i].w*g.w;}
#pragma unroll
        for (int o=16;o>0;o>>=1) s+=__shfl_xor_sync(0xffffffffu,s,o);
        lg[e]=s+gb[e];
    }
    if (lane==0){
        int e0=0; float m0=lg[0];
#pragma unroll
        for (int e=1;e<8;e++) if (lg[e]>m0){m0=lg[e];e0=e;}
        int e1=-1; float m1=-3.4e38f;
#pragma unroll
        for (int e=0;e<8;e++) if (e!=e0 && lg[e]>m1){m1=lg[e];e1=e;}
        float w0=1.f/(1.f+expf(m1-m0));
        g_re[2*n]=e0; g_rw[2*n]=w0; g_re[2*n+1]=e1; g_rw[2*n+1]=1.f-w0;
        atomicAdd(&g_cnt[e0],1); atomicAdd(&g_cnt[e1],1);
    }
}

__global__ void k_scan() {
    if (threadIdx.x==0){
        int run=0;
        for (int e=0;e<E_;e++){
            g_cur[e]=run;
            int pt=(g_cnt[e]+63)>>6, t0=run>>6;
            for (int t=0;t<pt;t++) g_texp[t0+t]=e;
            run+=pt<<6;
        }
        for (int t=run>>6;t<MAX_TILES;t++) g_texp[t]=-1;
    }
    for (int i=threadIdx.x;i<P_PAD;i+=blockDim.x){ g_ptok[i]=0; g_pw[i]=0.f; }
}

__global__ void k_assign() {
    int n=blockIdx.x*blockDim.x+threadIdx.x;
    if (n>=N_) return;
#pragma unroll
    for (int k=0;k<2;k++){
        int e=g_re[2*n+k];
        int pos=atomicAdd(&g_cur[e],1);
        g_ptok[pos]=n; g_pw[pos]=g_rw[2*n+k]; g_entry[2*n+k]=pos;
    }
}

#define T1_SMEM (256 + 2*(2*64*44*4) + 2*32*72*4)
__global__ __launch_bounds__(256,1) void k_t1() {
    int e=g_texp[blockIdx.x]; if (e<0) return;
    int p0=blockIdx.x*64;
    extern __shared__ __align__(16) char smraw[];
    int*   tok=(int*)smraw;
    float* ah=(float*)(smraw+256);
    float* al=ah+2*64*44;
    float* bs=al+2*64*44;
    int tid=threadIdx.x, warp=tid>>5, lane=tid&31;
    int grp=lane>>2, tig=lane&3, wm=warp>>2, wn=warp&3;
    if (tid<64) tok[tid]=g_ptok[p0+tid];
    __syncthreads();
    const size_t u1b=(size_t)e*D_*R_;
    const int NC=D_/32;
    auto issue=[&](int c){
        int buf=c&1, k0=c*32;
        float* ahb=ah+buf*64*44; float* alb=al+buf*64*44; float* bsb=bs+buf*32*72;
#pragma unroll
        for (int j=0;j<2;j++){int idx=tid+j*256, row=idx>>3, cq=idx&7;
            size_t src=(size_t)tok[row]*D_+k0+cq*4;
            cpa(&ahb[row*44+cq*4], g_xh+src); cpa(&alb[row*44+cq*4], g_xl+src);}
#pragma unroll
        for (int j=0;j<2;j++){int idx=tid+j*256, row=idx>>4, cq=idx&15;
            cpa(&bsb[row*72+cq*4], g_u1t+u1b+(size_t)(k0+row)*R_+cq*4);}
    };
    float acc[2][2][4];
#pragma unroll
    for (int a=0;a<2;a++)
#pragma unroll
        for (int b=0;b<2;b++)
#pragma unroll
            for (int q=0;q<4;q++) acc[a][b][q]=0.f;
    issue(0); CPC;
    for (int c=0;c<NC;c++){
        if (c>0) __syncthreads();
        if (c+1<NC){ issue(c+1); CPC; CPW1; } else { CPW0; }
        __syncthreads();
        int buf=c&1;
        const float* ahb=ah+buf*64*44; const float* alb=al+buf*64*44; const float* bsb=bs+buf*32*72;
#pragma unroll
        for (int kk=0;kk<4;kk++){
            float fh[2][4], fl[2][4];
#pragma unroll
            for (int mi=0;mi<2;mi++){
                ldA(fh[mi],ahb,44,wm*32+mi*16+grp,kk*8+tig);
                ldA(fl[mi],alb,44,wm*32+mi*16+grp,kk*8+tig);}
#pragma unroll
            for (int ni=0;ni<2;ni++){
                uint32_t b0,b1; ldB(b0,b1,bsb,72,kk*8+tig,wn*16+ni*8+grp);
#pragma unroll
                for (int mi=0;mi<2;mi++){ mma8(acc[mi][ni],fh[mi],b0,b1); mma8(acc[mi][ni],fl[mi],b0,b1); }
            }
        }
    }
#pragma unroll
    for (int mi=0;mi<2;mi++)
#pragma unroll
        for (int ni=0;ni<2;ni++){
            int r0=wm*32+mi*16+grp, c0=wn*16+ni*8+tig*2;
#pragma unroll
            for (int q=0;q<4;q++){
                int rr=r0+(q>>1)*8, cc=c0+(q&1);
                float v=acc[mi][ni][q], h=rna_tf32(v), l=rna_tf32(v-h);
                g_t1h[(size_t)(p0+rr)*R_+cc]=h; g_t1l[(size_t)(p0+rr)*R_+cc]=l;
            }
        }
}

#define MID_SMEM (2*(64*76*4) + 64*140*4 + 2*64*136*4 + 2*128*72*4 + 2*128*4)
__global__ __launch_bounds__(256,1) void k_mid(const float* __restrict__ b1) {
    int e=g_texp[blockIdx.x]; if (e<0) return;
    int p0=blockIdx.x*64;
    extern __shared__ __align__(16) char smraw[];
    float* t1hs=(float*)smraw;
    float* t1ls=t1hs+64*76;
    float* hsm=t1ls+64*76;
    float* v1s=hsm+64*140;
    float* u2s=v1s+2*64*136;
    float* b1s=u2s+2*128*72;
    int tid=threadIdx.x, warp=tid>>5, lane=tid&31;
    int grp=lane>>2, tig=lane&3, wm=warp>>2, wn=warp&3;
    const size_t v1b0=(size_t)e*R_*H_, u2b0=(size_t)e*H_*R_;
    const float* b1e=b1+(size_t)e*H_;
    const int NC=H_/128;
    auto issue=[&](int c){
        int buf=c&1, hc=c*128;
        float* v1b=v1s+buf*64*136; float* u2b=u2s+buf*128*72; float* b1b=b1s+buf*128;
#pragma unroll
        for (int j=0;j<8;j++){int idx=tid+j*256, row=idx>>5, cq=idx&31;
            cpa(&v1b[row*136+cq*4], g_v1t+v1b0+(size_t)row*H_+hc+cq*4);}
#pragma unroll
        for (int j=0;j<8;j++){int idx=tid+j*256, row=idx>>4, cq=idx&15;
            cpa(&u2b[row*72+cq*4], g_u2t+u2b0+(size_t)(hc+row)*R_+cq*4);}
        if (tid<32) cpa(&b1b[tid*4], b1e+hc+tid*4);
    };
#pragma unroll
    for (int j=0;j<4;j++){int idx=tid+j*256, row=idx>>4, cq=idx&15;
        cpa(&t1hs[row*76+cq*4], g_t1h+(size_t)(p0+row)*R_+cq*4);
        cpa(&t1ls[row*76+cq*4], g_t1l+(size_t)(p0+row)*R_+cq*4);}
    issue(0); CPC;
    float acc2[2][2][4];
#pragma unroll
    for (int a=0;a<2;a++)
#pragma unroll
        for (int b=0;b<2;b++)
#pragma unroll
            for (int q=0;q<4;q++) acc2[a][b][q]=0.f;
    for (int c=0;c<NC;c++){
        if (c>0) __syncthreads();
        if (c+1<NC){ issue(c+1); CPC; CPW1; } else { CPW0; }
        __syncthreads();
        int buf=c&1;
        const float* v1b=v1s+buf*64*136; const float* u2b=u2s+buf*128*72; const float* b1b=b1s+buf*128;
        float acc1[2][4][4];
#pragma unroll
        for (int a=0;a<2;a++)
#pragma unroll
            for (int b=0;b<4;b++)
#pragma unroll
                for (int q=0;q<4;q++) acc1[a][b][q]=0.f;
#pragma unroll
        for (int kk=0;kk<8;kk++){
            float fh[2][4], fl[2][4];
#pragma unroll
            for (int mi=0;mi<2;mi++){
                ldA(fh[mi],t1hs,76,wm*32+mi*16+grp,kk*8+tig);
                ldA(fl[mi],t1ls,76,wm*32+mi*16+grp,kk*8+tig);}
#pragma unroll
            for (int ni=0;ni<4;ni++){
                uint32_t b0,b1r; ldB(b0,b1r,v1b,136,kk*8+tig,wn*32+ni*8+grp);
#pragma unroll
                for (int mi=0;mi<2;mi++){ mma8(acc1[mi][ni],fh[mi],b0,b1r); mma8(acc1[mi][ni],fl[mi],b0,b1r); }
            }
        }
#pragma unroll
        for (int mi=0;mi<2;mi++)
#pragma unroll
            for (int ni=0;ni<4;ni++){
                int r0=wm*32+mi*16+grp, c0=wn*32+ni*8+tig*2;
                float bb0=b1b[c0], bb1=b1b[c0+1];
                hsm[r0*140+c0]    =rna_tf32(fmaxf(acc1[mi][ni][0]+bb0,0.f));
                hsm[r0*140+c0+1]  =rna_tf32(fmaxf(acc1[mi][ni][1]+bb1,0.f));
                hsm[(r0+8)*140+c0]  =rna_tf32(fmaxf(acc1[mi][ni][2]+bb0,0.f));
                hsm[(r0+8)*140+c0+1]=rna_tf32(fmaxf(acc1[mi][ni][3]+bb1,0.f));
            }
        __syncthreads();
#pragma unroll
        for (int kk=0;kk<16;kk++){
            float fa[2][4];
#pragma unroll
            for (int mi=0;mi<2;mi++) ldA(fa[mi],hsm,140,wm*32+mi*16+grp,kk*8+tig);
#pragma unroll
            for (int ni=0;ni<2;ni++){
                uint32_t b0,b1r; ldB(b0,b1r,u2b,72,kk*8+tig,wn*16+ni*8+grp);
#pragma unroll
                for (int mi=0;mi<2;mi++) mma8(acc2[mi][ni],fa[mi],b0,b1r);
            }
        }
    }
#pragma unroll
    for (int mi=0;mi<2;mi++)
#pragma unroll
        for (int ni=0;ni<2;ni++){
            int r0=wm*32+mi*16+grp, c0=wn*16+ni*8+tig*2;
#pragma unroll
            for (int q=0;q<4;q++){
                int rr=r0+(q>>1)*8, cc=c0+(q&1);
                float v=acc2[mi][ni][q], h=rna_tf32(v), l=rna_tf32(v-h);
                g_t2h[(size_t)(p0+rr)*R_+cc]=h; g_t2l[(size_t)(p0+rr)*R_+cc]=l;
            }
        }
}

#define Y_SMEM (2*(64*76*4) + 2*64*136*4 + 2*128*4 + 64*4)
__global__ __launch_bounds__(256,1) void k_y(const float* __restrict__ b2) {
    int e=g_texp[blockIdx.x]; if (e<0) return;
    int p0=blockIdx.x*64;
    extern __shared__ __align__(16) char smraw[];
    float* t2hs=(float*)smraw;
    float* t2ls=t2hs+64*76;
    float* v2s=t2ls+64*76;
    float* b2s=v2s+2*64*136;
    float* ws=b2s+2*128;
    int tid=threadIdx.x, warp=tid>>5, lane=tid&31;
    int grp=lane>>2, tig=lane&3, wm=warp>>2, wn=warp&3;
    const size_t v2b0=(size_t)e*R_*D_;
    const float* b2e=b2+(size_t)e*D_;
    const int NC=D_/128;
    auto issue=[&](int c){
        int buf=c&1, dc=c*128;
        float* v2b=v2s+buf*64*136; float* b2b=b2s+buf*128;
#pragma unroll
        for (int j=0;j<8;j++){int idx=tid+j*256, row=idx>>5, cq=idx&31;
            cpa(&v2b[row*136+cq*4], g_v2t+v2b0+(size_t)row*D_+dc+cq*4);}
        if (tid<32) cpa(&b2b[tid*4], b2e+dc+tid*4);
    };
    if (tid<64) ws[tid]=g_pw[p0+tid];
#pragma unroll
    for (int j=0;j<4;j++){int idx=tid+j*256, row=idx>>4, cq=idx&15;
        cpa(&t2hs[row*76+cq*4], g_t2h+(size_t)(p0+row)*R_+cq*4);
        cpa(&t2ls[row*76+cq*4], g_t2l+(size_t)(p0+row)*R_+cq*4);}
    issue(0); CPC;
    for (int c=0;c<NC;c++){
        if (c>0) __syncthreads();
        if (c+1<NC){ issue(c+1); CPC; CPW1; } else { CPW0; }
        __syncthreads();
        int buf=c&1, dc=c*128;
        const float* v2b=v2s+buf*64*136; const float* b2b=b2s+buf*128;
        float acc[2][4][4];
#pragma unroll
        for (int a=0;a<2;a++)
#pragma unroll
            for (int b=0;b<4;b++)
#pragma unroll
                for (int q=0;q<4;q++) acc[a][b][q]=0.f;
#pragma unroll
        for (int kk=0;kk<8;kk++){
            float fh[2][4], fl[2][4];
#pragma unroll
            for (int mi=0;mi<2;mi++){
                ldA(fh[mi],t2hs,76,wm*32+mi*16+grp,kk*8+tig);
                ldA(fl[mi],t2ls,76,wm*32+mi*16+grp,kk*8+tig);}
#pragma unroll
            for (int ni=0;ni<4;ni++){
                uint32_t b0,b1r; ldB(b0,b1r,v2b,136,kk*8+tig,wn*32+ni*8+grp);
#pragma unroll
                for (int mi=0;mi<2;mi++){ mma8(acc[mi][ni],fh[mi],b0,b1r); mma8(acc[mi][ni],fl[mi],b0,b1r); }
            }
        }
#pragma unroll
        for (int mi=0;mi<2;mi++)
#pragma unroll
            for (int ni=0;ni<4;ni++){
                int r0=wm*32+mi*16+grp, c0=wn*32+ni*8+tig*2;
                float w0v=ws[r0], w1v=ws[r0+8], bb0=b2b[c0], bb1=b2b[c0+1];
                float2 o0=make_float2(w0v*(acc[mi][ni][0]+bb0), w0v*(acc[mi][ni][1]+bb1));
                float2 o1=make_float2(w1v*(acc[mi][ni][2]+bb0), w1v*(acc[mi][ni][3]+bb1));
                *(float2*)(g_py+(size_t)(p0+r0)*D_+dc+c0)=o0;
                *(float2*)(g_py+(size_t)(p0+r0+8)*D_+dc+c0)=o1;
            }
    }
}

__global__ void k_combine(float* __restrict__ out) {
    int n=blockIdx.x;
    int pa=g_entry[2*n], pb=g_entry[2*n+1];
    const float4* a=(const float4*)(g_py+(size_t)pa*D_);
    const float4* b=(const float4*)(g_py+(size_t)pb*D_);
    float4* o=(float4*)(out+(size_t)n*D_);
    for (int j=threadIdx.x;j<D_/4;j+=blockDim.x){
        float4 va=a[j], vb=b[j];
        o[j]=make_float4(va.x+vb.x, va.y+vb.y, va.z+vb.z, va.w+vb.w);
    }
}

extern "C" void kernel_launch(void* const* d_in, const int* in_sizes, int n_in,
                              void* d_out, int out_size) {
    const float* x  = (const float*)d_in[0];
    const float* u1 = (const float*)d_in[1];
    const float* v1 = (const float*)d_in[2];
    const float* b1 = (const float*)d_in[3];
    const float* u2 = (const float*)d_in[4];
    const float* v2 = (const float*)d_in[5];
    const float* b2 = (const float*)d_in[6];
    const float* gw = (const float*)d_in[7];
    const float* gb = (const float*)d_in[8];
    float* out = (float*)d_out;

    static bool attr_done = false;
    if (!attr_done) {
        cudaFuncSetAttribute(k_t1,  cudaFuncAttributeMaxDynamicSharedMemorySize, T1_SMEM);
        cudaFuncSetAttribute(k_mid, cudaFuncAttributeMaxDynamicSharedMemorySize, MID_SMEM);
        cudaFuncSetAttribute(k_y,   cudaFuncAttributeMaxDynamicSharedMemorySize, Y_SMEM);
        attr_done = true;
    }

    k_init<<<1, 32>>>();
    k_pre<<<2048, 256>>>(u1, v1, u2, v2, x);
    k_route<<<512, 256>>>(x, gw, gb);
    k_scan<<<1, 256>>>();
    k_assign<<<16, 256>>>();
    k_t1<<<MAX_TILES, 256, T1_SMEM>>>();
    k_mid<<<MAX_TILES, 256, MID_SMEM>>>(b1);
    k_y<<<MAX_TILES, 256, Y_SMEM>>>(b2);
    k_combine<<<N_, 256>>>(out);
}

// round 4
// speedup vs baseline: 1.3590x; 1.3590x over previous
#include <cuda_runtime.h>
#include <cstdint>
#include <math.h>

#define E_ 8
#define D_ 2048
#define H_ 8192
#define R_ 64
#define N_ 4096
#define T64 144
#define T128 72
#define P_PAD (T128*128)

__device__ __align__(16) float g_t1 [(size_t)P_PAD*R_];
__device__ __align__(16) float g_t2a[(size_t)P_PAD*R_];
__device__ __align__(16) float g_t2b[(size_t)P_PAD*R_];
__device__ __align__(16) float g_py [(size_t)P_PAD*D_];
__device__ int   g_ptok[P_PAD];
__device__ float g_pw  [P_PAD];
__device__ int   g_entry[2*N_];
__device__ int   g_re[2*N_];
__device__ float g_rw[2*N_];
__device__ int   g_cnt[E_];
__device__ int   g_cur[E_];
__device__ int   g_te64[T64];
__device__ int   g_te128[T128];

__device__ __forceinline__ float rna(float f) {
    uint32_t u; asm("cvt.rna.tf32.f32 %0, %1;" : "=r"(u) : "f"(f));
    return __uint_as_float(u);
}
__device__ __forceinline__ uint32_t rnab(float f) {
    uint32_t u; asm("cvt.rna.tf32.f32 %0, %1;" : "=r"(u) : "f"(f));
    return u;
}
__device__ __forceinline__ void mma8(float c[4], const float a[4], uint32_t b0, uint32_t b1) {
    asm volatile("mma.sync.aligned.m16n8k8.row.col.f32.tf32.tf32.f32 "
        "{%0,%1,%2,%3}, {%4,%5,%6,%7}, {%8,%9}, {%0,%1,%2,%3};"
        : "+f"(c[0]), "+f"(c[1]), "+f"(c[2]), "+f"(c[3])
        : "r"(__float_as_uint(a[0])), "r"(__float_as_uint(a[1])),
          "r"(__float_as_uint(a[2])), "r"(__float_as_uint(a[3])), "r"(b0), "r"(b1));
}
// A fragment, values already tf32-rounded in smem
__device__ __forceinline__ void ldA(float a[4], const float* s, int st, int r, int k) {
    a[0]=s[r*st+k]; a[1]=s[(r+8)*st+k]; a[2]=s[r*st+k+4]; a[3]=s[(r+8)*st+k+4];
}
// A fragment from raw fp32 smem, round after load
__device__ __forceinline__ void ldAc(float a[4], const float* s, int st, int r, int k) {
    a[0]=rna(s[r*st+k]); a[1]=rna(s[(r+8)*st+k]); a[2]=rna(s[r*st+k+4]); a[3]=rna(s[(r+8)*st+k+4]);
}
// B fragment from raw fp32 smem [k][n], round after load
__device__ __forceinline__ void ldBc(uint32_t& b0, uint32_t& b1, const float* s, int st, int k, int n) {
    b0=rnab(s[k*st+n]); b1=rnab(s[(k+4)*st+n]);
}
__device__ __forceinline__ void cpa(void* s, const void* g) {
    uint32_t sa=(uint32_t)__cvta_generic_to_shared(s);
    asm volatile("cp.async.cg.shared.global [%0], [%1], 16;" :: "r"(sa), "l"(g));
}
#define CPC  asm volatile("cp.async.commit_group;" ::: "memory")
#define CPW1 asm volatile("cp.async.wait_group 1;" ::: "memory")
#define CPW0 asm volatile("cp.async.wait_group 0;" ::: "memory")

__global__ void k_init() { if (threadIdx.x < E_) g_cnt[threadIdx.x] = 0; }

__global__ __launch_bounds__(256) void k_route(const float* __restrict__ x,
        const float* __restrict__ gw, const float* __restrict__ gb) {
    int warp=threadIdx.x>>5, lane=threadIdx.x&31;
    int n = blockIdx.x*8 + warp;
    const float4* xr = (const float4*)(x + (size_t)n*D_);
    float4 xv[16];
#pragma unroll
    for (int i=0;i<16;i++) xv[i]=xr[lane+i*32];
    float lg[8];
#pragma unroll
    for (int e=0;e<8;e++){
        const float4* gr=(const float4*)(gw+(size_t)e*D_);
        float s=0.f;
#pragma unroll
        for (int i=0;i<16;i++){float4 g=gr[lane+i*32];
            s+=xv[i].x*g.x+xv[i].y*g.y+xv[i].z*g.z+xv[i].w*g.w;}
#pragma unroll
        for (int o=16;o>0;o>>=1) s+=__shfl_xor_sync(0xffffffffu,s,o);
        lg[e]=s+gb[e];
    }
    if (lane==0){
        int e0=0; float m0=lg[0];
#pragma unroll
        for (int e=1;e<8;e++) if (lg[e]>m0){m0=lg[e];e0=e;}
        int e1=-1; float m1=-3.4e38f;
#pragma unroll
        for (int e=0;e<8;e++) if (e!=e0 && lg[e]>m1){m1=lg[e];e1=e;}
        float w0=1.f/(1.f+expf(m1-m0));
        g_re[2*n]=e0; g_rw[2*n]=w0; g_re[2*n+1]=e1; g_rw[2*n+1]=1.f-w0;
        atomicAdd(&g_cnt[e0],1); atomicAdd(&g_cnt[e1],1);
    }
}

__global__ void k_scan() {
    if (threadIdx.x==0){
        int run=0;
        for (int e=0;e<E_;e++){
            g_cur[e]=run;
            int seg=((g_cnt[e]+127)>>7)<<7;   // 128-aligned segments
            for (int t=run>>6;t<(run+seg)>>6;t++) g_te64[t]=e;
            for (int t=run>>7;t<(run+seg)>>7;t++) g_te128[t]=e;
            run+=seg;
        }
        for (int t=run>>6;t<T64;t++)  g_te64[t]=-1;
        for (int t=run>>7;t<T128;t++) g_te128[t]=-1;
    }
    for (int i=threadIdx.x;i<P_PAD;i+=blockDim.x){ g_ptok[i]=0; g_pw[i]=0.f; }
}

__global__ void k_assign() {
    int n=blockIdx.x*blockDim.x+threadIdx.x;
    if (n>=N_) return;
#pragma unroll
    for (int k=0;k<2;k++){
        int e=g_re[2*n+k];
        int pos=atomicAdd(&g_cur[e],1);
        g_ptok[pos]=n; g_pw[pos]=g_rw[2*n+k]; g_entry[2*n+k]=pos;
    }
}

// ---------------- t1 = rna(x) @ rna(u1) : tiles of 64 pairs -----------------
#define T1_SMEM (256 + 2*64*36*4 + 2*32*72*4)
__global__ __launch_bounds__(256) void k_t1(const float* __restrict__ x,
                                            const float* __restrict__ u1) {
    int e=g_te64[blockIdx.x]; if (e<0) return;
    int p0=blockIdx.x*64;
    extern __shared__ __align__(16) char smraw[];
    int*   tok=(int*)smraw;
    float* as=(float*)(smraw+256);           // 2 x 64 x 36
    float* bs=as+2*64*36;                    // 2 x 32 x 72
    int tid=threadIdx.x, warp=tid>>5, lane=tid&31;
    int grp=lane>>2, tig=lane&3, wm=warp>>2, wn=warp&3;
    if (tid<64) tok[tid]=g_ptok[p0+tid];
    __syncthreads();
    const float* u1e = u1 + (size_t)e*D_*R_;
    const int NC=D_/32;
    auto issue=[&](int c){
        int buf=c&1, k0=c*32;
        float* ab=as+buf*64*36; float* bb=bs+buf*32*72;
#pragma unroll
        for (int j=0;j<2;j++){int idx=tid+j*256, row=idx>>3, cq=idx&7;
            cpa(&ab[row*36+cq*4], x+(size_t)tok[row]*D_+k0+cq*4);}
#pragma unroll
        for (int j=0;j<2;j++){int idx=tid+j*256, row=idx>>4, cq=idx&15;
            cpa(&bb[row*72+cq*4], u1e+(size_t)(k0+row)*R_+cq*4);}
    };
    float acc[2][2][4];
#pragma unroll
    for (int a=0;a<2;a++)
#pragma unroll
        for (int b=0;b<2;b++)
#pragma unroll
            for (int q=0;q<4;q++) acc[a][b][q]=0.f;
    issue(0); CPC;
    for (int c=0;c<NC;c++){
        if (c>0) __syncthreads();
        if (c+1<NC){ issue(c+1); CPC; CPW1; } else { CPW0; }
        __syncthreads();
        int buf=c&1;
        const float* ab=as+buf*64*36; const float* bb=bs+buf*32*72;
#pragma unroll
        for (int kk=0;kk<4;kk++){
            float fa[2][4];
#pragma unroll
            for (int mi=0;mi<2;mi++) ldAc(fa[mi],ab,36,wm*32+mi*16+grp,kk*8+tig);
#pragma unroll
            for (int ni=0;ni<2;ni++){
                uint32_t b0,b1; ldBc(b0,b1,bb,72,kk*8+tig,wn*16+ni*8+grp);
#pragma unroll
                for (int mi=0;mi<2;mi++) mma8(acc[mi][ni],fa[mi],b0,b1);
            }
        }
    }
#pragma unroll
    for (int mi=0;mi<2;mi++)
#pragma unroll
        for (int ni=0;ni<2;ni++){
            int r0=wm*32+mi*16+grp, c0=wn*16+ni*8+tig*2;
#pragma unroll
            for (int q=0;q<4;q++){
                int rr=r0+(q>>1)*8, cc=c0+(q&1);
                g_t1[(size_t)(p0+rr)*R_+cc]=rna(acc[mi][ni][q]);
            }
        }
}

// -------- mid: t2_partial = relu(t1@v1+b1)@u2 over one H-half ---------------
// grid = T128*2 ; tile = bx>>1 (128 pairs), half = bx&1 (H/2 = 4096, 64 chunks of 64)
#define MID_SMEM (128*76*4 + 128*76*4 + 2*64*72*4 + 2*64*72*4 + 2*64*4)
__global__ __launch_bounds__(256,1) void k_mid(const float* __restrict__ v1,
                                               const float* __restrict__ u2,
                                               const float* __restrict__ b1) {
    int tile=blockIdx.x>>1, half=blockIdx.x&1;
    int e=g_te128[tile]; if (e<0) return;
    int p0=tile*128, hbase=half*(H_/2);
    extern __shared__ __align__(16) char smraw[];
    float* t1s=(float*)smraw;                // 128 x 76
    float* hsm=t1s+128*76;                   // 128 x 76
    float* v1s=hsm+128*76;                   // 2 x 64 x 72
    float* u2s=v1s+2*64*72;                  // 2 x 64 x 72
    float* b1s=u2s+2*64*72;                  // 2 x 64
    int tid=threadIdx.x, warp=tid>>5, lane=tid&31;
    int grp=lane>>2, tig=lane&3, wm=warp&3, wn=warp>>2;
    const float* v1e=v1+(size_t)e*R_*H_;
    const float* u2e=u2+(size_t)e*H_*R_;
    const float* b1e=b1+(size_t)e*H_;
    const int NC=(H_/2)/64;
    auto issue=[&](int c){
        int buf=c&1, hc=hbase+c*64;
        float* vb=v1s+buf*64*72; float* ub=u2s+buf*64*72; float* bb=b1s+buf*64;
#pragma unroll
        for (int j=0;j<4;j++){int idx=tid+j*256, row=idx>>4, cq=idx&15;
            cpa(&vb[row*72+cq*4], v1e+(size_t)row*H_+hc+cq*4);}
#pragma unroll
        for (int j=0;j<4;j++){int idx=tid+j*256, row=idx>>4, cq=idx&15;
            cpa(&ub[row*72+cq*4], u2e+(size_t)(hc+row)*R_+cq*4);}
        if (tid<16) cpa(&bb[tid*4], b1e+hc+tid*4);
    };
    // prologue: t1 tile (pre-rounded) + chunk 0
#pragma unroll
    for (int j=0;j<8;j++){int idx=tid+j*256, row=idx>>4, cq=idx&15;
        cpa(&t1s[row*76+cq*4], g_t1+(size_t)(p0+row)*R_+cq*4);}
    issue(0); CPC;
    float acc2[2][4][4];
#pragma unroll
    for (int a=0;a<2;a++)
#pragma unroll
        for (int b=0;b<4;b++)
#pragma unroll
            for (int q=0;q<4;q++) acc2[a][b][q]=0.f;
    for (int c=0;c<NC;c++){
        if (c>0) __syncthreads();                  // prev G2 done (hsm + old weight buf free)
        if (c+1<NC){ issue(c+1); CPC; CPW1; } else { CPW0; }
        __syncthreads();                           // chunk c data visible
        int buf=c&1;
        const float* vb=v1s+buf*64*72; const float* ub=u2s+buf*64*72; const float* bb=b1s+buf*64;
        // G1: [128 x 64] = t1 @ v1c   (K = R = 64)
        float acc1[2][4][4];
#pragma unroll
        for (int a=0;a<2;a++)
#pragma unroll
            for (int b=0;b<4;b++)
#pragma unroll
                for (int q=0;q<4;q++) acc1[a][b][q]=0.f;
#pragma unroll
        for (int kk=0;kk<8;kk++){
            float fa[2][4];
#pragma unroll
            for (int mi=0;mi<2;mi++) ldA(fa[mi],t1s,76,wm*32+mi*16+grp,kk*8+tig);
#pragma unroll
            for (int ni=0;ni<4;ni++){
                uint32_t b0,b1r; ldBc(b0,b1r,vb,72,kk*8+tig,wn*32+ni*8+grp);
#pragma unroll
                for (int mi=0;mi<2;mi++) mma8(acc1[mi][ni],fa[mi],b0,b1r);
            }
        }
#pragma unroll
        for (int mi=0;mi<2;mi++)
#pragma unroll
            for (int ni=0;ni<4;ni++){
                int r0=wm*32+mi*16+grp, c0=wn*32+ni*8+tig*2;
                float bb0=bb[c0], bb1=bb[c0+1];
                hsm[r0*76+c0]      =rna(fmaxf(acc1[mi][ni][0]+bb0,0.f));
                hsm[r0*76+c0+1]    =rna(fmaxf(acc1[mi][ni][1]+bb1,0.f));
                hsm[(r0+8)*76+c0]  =rna(fmaxf(acc1[mi][ni][2]+bb0,0.f));
                hsm[(r0+8)*76+c0+1]=rna(fmaxf(acc1[mi][ni][3]+bb1,0.f));
            }
        __syncthreads();                           // h visible
        // G2: acc2 += h @ u2c   (K = 64)
#pragma unroll
        for (int kk=0;kk<8;kk++){
            float fa[2][4];
#pragma unroll
            for (int mi=0;mi<2;mi++) ldA(fa[mi],hsm,76,wm*32+mi*16+grp,kk*8+tig);
#pragma unroll
            for (int ni=0;ni<4;ni++){
                uint32_t b0,b1r; ldBc(b0,b1r,ub,72,kk*8+tig,wn*32+ni*8+grp);
#pragma unroll
                for (int mi=0;mi<2;mi++) mma8(acc2[mi][ni],fa[mi],b0,b1r);
            }
        }
    }
    float* dst = half ? g_t2b : g_t2a;
#pragma unroll
    for (int mi=0;mi<2;mi++)
#pragma unroll
        for (int ni=0;ni<4;ni++){
            int r0=wm*32+mi*16+grp, c0=wn*32+ni*8+tig*2;
            *(float2*)(dst+(size_t)(p0+r0)*R_+c0)   = make_float2(acc2[mi][ni][0],acc2[mi][ni][1]);
            *(float2*)(dst+(size_t)(p0+r0+8)*R_+c0) = make_float2(acc2[mi][ni][2],acc2[mi][ni][3]);
        }
}

// ---------------- y = w * (t2 @ v2 + b2) : tiles of 64 pairs -----------------
#define Y_SMEM (64*76*4 + 2*64*136*4 + 2*128*4 + 64*4)
__global__ __launch_bounds__(256) void k_y(const float* __restrict__ v2,
                                           const float* __restrict__ b2) {
    int e=g_te64[blockIdx.x]; if (e<0) return;
    int p0=blockIdx.x*64;
    extern __shared__ __align__(16) char smraw[];
    float* t2s=(float*)smraw;                // 64 x 76
    float* v2s=t2s+64*76;                    // 2 x 64 x 136
    float* b2s=v2s+2*64*136;                 // 2 x 128
    float* ws=b2s+2*128;                     // 64
    int tid=threadIdx.x, warp=tid>>5, lane=tid&31;
    int grp=lane>>2, tig=lane&3, wm=warp>>2, wn=warp&3;
    const float* v2e=v2+(size_t)e*R_*D_;
    const float* b2e=b2+(size_t)e*D_;
    const int NC=D_/128;
    auto issue=[&](int c){
        int buf=c&1, dc=c*128;
        float* vb=v2s+buf*64*136; float* bb=b2s+buf*128;
#pragma unroll
        for (int j=0;j<8;j++){int idx=tid+j*256, row=idx>>5, cq=idx&31;
            cpa(&vb[row*136+cq*4], v2e+(size_t)row*D_+dc+cq*4);}
        if (tid<32) cpa(&bb[tid*4], b2e+dc+tid*4);
    };
    if (tid<64) ws[tid]=g_pw[p0+tid];
    // t2 = rna(t2a + t2b)
#pragma unroll
    for (int j=0;j<4;j++){
        int i=tid+j*256, row=i>>4, cq=i&15;
        float4 a=((const float4*)g_t2a)[(size_t)p0*16+i];
        float4 b=((const float4*)g_t2b)[(size_t)p0*16+i];
        t2s[row*76+cq*4+0]=rna(a.x+b.x); t2s[row*76+cq*4+1]=rna(a.y+b.y);
        t2s[row*76+cq*4+2]=rna(a.z+b.z); t2s[row*76+cq*4+3]=rna(a.w+b.w);
    }
    issue(0); CPC;
    for (int c=0;c<NC;c++){
        if (c>0) __syncthreads();
        if (c+1<NC){ issue(c+1); CPC; CPW1; } else { CPW0; }
        __syncthreads();
        int buf=c&1, dc=c*128;
        const float* vb=v2s+buf*64*136; const float* bb=b2s+buf*128;
        float acc[2][4][4];
#pragma unroll
        for (int a=0;a<2;a++)
#pragma unroll
            for (int b=0;b<4;b++)
#pragma unroll
                for (int q=0;q<4;q++) acc[a][b][q]=0.f;
#pragma unroll
        for (int kk=0;kk<8;kk++){
            float fa[2][4];
#pragma unroll
            for (int mi=0;mi<2;mi++) ldA(fa[mi],t2s,76,wm*32+mi*16+grp,kk*8+tig);
#pragma unroll
            for (int ni=0;ni<4;ni++){
                uint32_t b0,b1r; ldBc(b0,b1r,vb,136,kk*8+tig,wn*32+ni*8+grp);
#pragma unroll
                for (int mi=0;mi<2;mi++) mma8(acc[mi][ni],fa[mi],b0,b1r);
            }
        }
#pragma unroll
        for (int mi=0;mi<2;mi++)
#pragma unroll
            for (int ni=0;ni<4;ni++){
                int r0=wm*32+mi*16+grp, c0=wn*32+ni*8+tig*2;
                float w0v=ws[r0], w1v=ws[r0+8], bb0=bb[c0], bb1=bb[c0+1];
                *(float2*)(g_py+(size_t)(p0+r0)*D_+dc+c0)   =
                    make_float2(w0v*(acc[mi][ni][0]+bb0), w0v*(acc[mi][ni][1]+bb1));
                *(float2*)(g_py+(size_t)(p0+r0+8)*D_+dc+c0) =
                    make_float2(w1v*(acc[mi][ni][2]+bb0), w1v*(acc[mi][ni][3]+bb1));
            }
    }
}

__global__ void k_combine(float* __restrict__ out) {
    int n=blockIdx.x;
    int pa=g_entry[2*n], pb=g_entry[2*n+1];
    const float4* a=(const float4*)(g_py+(size_t)pa*D_);
    const float4* b=(const float4*)(g_py+(size_t)pb*D_);
    float4* o=(float4*)(out+(size_t)n*D_);
    for (int j=threadIdx.x;j<D_/4;j+=blockDim.x){
        float4 va=a[j], vb=b[j];
        o[j]=make_float4(va.x+vb.x, va.y+vb.y, va.z+vb.z, va.w+vb.w);
    }
}

extern "C" void kernel_launch(void* const* d_in, const int* in_sizes, int n_in,
                              void* d_out, int out_size) {
    const float* x  = (const float*)d_in[0];
    const float* u1 = (const float*)d_in[1];
    const float* v1 = (const float*)d_in[2];
    const float* b1 = (const float*)d_in[3];
    const float* u2 = (const float*)d_in[4];
    const float* v2 = (const float*)d_in[5];
    const float* b2 = (const float*)d_in[6];
    const float* gw = (const float*)d_in[7];
    const float* gb = (const float*)d_in[8];
    float* out = (float*)d_out;

    static bool attr_done = false;
    if (!attr_done) {
        cudaFuncSetAttribute(k_mid, cudaFuncAttributeMaxDynamicSharedMemorySize, MID_SMEM);
        cudaFuncSetAttribute(k_y,   cudaFuncAttributeMaxDynamicSharedMemorySize, Y_SMEM);
        attr_done = true;
    }

    k_init<<<1, 32>>>();
    k_route<<<512, 256>>>(x, gw, gb);
    k_scan<<<1, 256>>>();
    k_assign<<<16, 256>>>();
    k_t1<<<T64, 256, T1_SMEM>>>(x, u1);
    k_mid<<<T128*2, 256, MID_SMEM>>>(v1, u2, b1);
    k_y<<<T64, 256, Y_SMEM>>>(v2, b2);
    k_combine<<<N_, 256>>>(out);
}